// round 3
// baseline (speedup 1.0000x reference)
#include <cuda_runtime.h>
#include <math.h>

// ============================================================================
// DBTransformerLayer — staged-GEMM + FFMA2 (fma.rn.f32x2) formulation.
//   Node precompute: qkv_dst = x_dst @ Wi^T + bi ; kv_src = x_src @ Weff^T + beff
//   Edge phase:  attn -> o -> GEMM(wo)+LN1 fused -> GEMM(l1,relu)
//                -> GEMM(l2)+LN2+scatter fused ; counts ; divide
// ============================================================================

#define MAX_N 20000
#define MAX_E 100000

// ------------------------------- scratch -----------------------------------
__device__ float g_qkv_dst0[(size_t)MAX_N * 4 * 384];
__device__ float g_qkv_dst1[(size_t)MAX_N * 4 * 384];
__device__ float g_kv_src0[(size_t)MAX_N * 4 * 256];
__device__ float g_kv_src1[(size_t)MAX_N * 4 * 256];
__device__ float g_weff[2 * 256 * 128];
__device__ float g_beff[2 * 256];
__device__ int   g_cnt[2 * MAX_N];
__device__ float g_buf1[(size_t)MAX_E * 512];   // o (attn out)
__device__ float g_buf2[(size_t)MAX_E * 512];   // xln
__device__ float g_buf3[(size_t)MAX_E * 256];   // h (FF hidden)

// --------------------------- f32x2 helpers ----------------------------------
__device__ __forceinline__ void ffma2(unsigned long long& d,
                                      unsigned long long a, unsigned long long b) {
    asm("fma.rn.f32x2 %0, %1, %2, %0;" : "+l"(d) : "l"(a), "l"(b));
}
__device__ __forceinline__ unsigned long long fdup(float x) {
    unsigned long long r;
    asm("mov.b64 %0, {%1, %1};" : "=l"(r) : "f"(x));
    return r;
}
__device__ __forceinline__ float2 u2f(unsigned long long u) {
    float2 r;
    r.x = __uint_as_float((unsigned)u);
    r.y = __uint_as_float((unsigned)(u >> 32));
    return r;
}

// ------------------------------- zero --------------------------------------
__global__ void zero_kernel(float4* out, int n4, int* cnt, int nc) {
    int stride = gridDim.x * blockDim.x;
    for (int i = blockIdx.x * blockDim.x + threadIdx.x; i < n4; i += stride)
        out[i] = make_float4(0.f, 0.f, 0.f, 0.f);
    for (int i = blockIdx.x * blockDim.x + threadIdx.x; i < nc; i += stride) cnt[i] = 0;
}

// ------------------------------- counts ------------------------------------
__global__ void count_kernel(const int* __restrict__ eAB, const int* __restrict__ eBA,
                             int E0, int E1, int* cnt, int NB) {
    int stride = gridDim.x * blockDim.x;
    int total = E0 + E1;
    for (int i = blockIdx.x * blockDim.x + threadIdx.x; i < total; i += stride) {
        if (i < E0) atomicAdd(&cnt[eAB[E0 + i]], 1);
        else        atomicAdd(&cnt[NB + eBA[E1 + (i - E0)]], 1);
    }
}

// ------------------------ Weff = Wi[128:384] @ bw ---------------------------
__global__ void prep_weff(const float* __restrict__ wi, const float* __restrict__ bi,
                          const float* __restrict__ bw, const float* __restrict__ bb,
                          float* __restrict__ weff, float* __restrict__ beff) {
    int n = blockIdx.x, r = blockIdx.y, k = threadIdx.x;
    const float* wrow = wi + ((size_t)r * 384 + 128 + n) * 128;
    const float* bwr  = bw + (size_t)r * 16384;
    float acc = 0.f;
    for (int m = 0; m < 128; ++m) acc += wrow[m] * bwr[m * 128 + k];
    weff[((size_t)r * 256 + n) * 128 + k] = acc;

    __shared__ float red[128];
    red[k] = wrow[k] * bb[r * 128 + k];
    __syncthreads();
    for (int s = 64; s; s >>= 1) { if (k < s) red[k] += red[k + s]; __syncthreads(); }
    if (k == 0) beff[r * 256 + n] = bi[(size_t)r * 384 + 128 + n] + red[0];
}

// ---------------- GEMM2: C[M,*] = A[M,K] @ W[*,K]^T + b  (FFMA2) ------------
// Block tile 256(M) x (16*TN)(N), whole K in smem, per-thread 16x TN.
// MODE 0: plain store (+optional relu), col offset = blockIdx.y * NT
// MODE 1: +residual gather(x_dst via edge) + LN -> store to C (ldc=128)
// MODE 2: +residual (xres row-indexed) + LN -> atomicAdd scatter to outp
template<int TN, int MODE, bool RELU>
__global__ __launch_bounds__(256)
void gemm2(const float* __restrict__ A, const float* __restrict__ W,
           const float* __restrict__ bias, float* __restrict__ C,
           int M, int K, int ldc,
           const int* __restrict__ edge, int E,
           const float* __restrict__ xres,
           const float* __restrict__ lnw, const float* __restrict__ lnb,
           float* __restrict__ outp)
{
    extern __shared__ float sm[];
    const int NT = 16 * TN;
    float* As = sm;                  // [K][256]
    float* Ws = sm + (size_t)K * 256; // [K][NT]
    const int bm = blockIdx.x * 256;
    const int bn = blockIdx.y * NT;
    const int tid = threadIdx.x;
    const int tx = tid & 15, ty = tid >> 4;

    // ---- load A: each thread owns one row (bm+tid), all K ----
    {
        int gm = bm + tid;
        const float4* ap = (const float4*)(A + (size_t)gm * K);
        for (int qk = 0; qk < (K >> 2); ++qk) {
            float4 a = make_float4(0.f, 0.f, 0.f, 0.f);
            if (gm < M) a = ap[qk];
            As[(qk * 4 + 0) * 256 + tid] = a.x;
            As[(qk * 4 + 1) * 256 + tid] = a.y;
            As[(qk * 4 + 2) * 256 + tid] = a.z;
            As[(qk * 4 + 3) * 256 + tid] = a.w;
        }
    }
    // ---- load W ----
    {
        const int TPQ = 256 / NT;                 // qk groups per pass
        int n = tid & (NT - 1);
        int qg = tid / NT;
        const float4* wp = (const float4*)(W + (size_t)(bn + n) * K);
        for (int it = 0; it < K / (4 * TPQ); ++it) {
            int qk = qg + it * TPQ;
            float4 w = wp[qk];
            Ws[(qk * 4 + 0) * NT + n] = w.x;
            Ws[(qk * 4 + 1) * NT + n] = w.y;
            Ws[(qk * 4 + 2) * NT + n] = w.z;
            Ws[(qk * 4 + 3) * NT + n] = w.w;
        }
    }
    __syncthreads();

    // ---- compute ----
    unsigned long long acc[8][TN];
    #pragma unroll
    for (int i = 0; i < 8; ++i)
        #pragma unroll
        for (int j = 0; j < TN; ++j) acc[i][j] = 0ull;

    const float* Abase = As + ty * 16;
    const float* Wbase = Ws + tx * TN;
    #pragma unroll 4
    for (int k = 0; k < K; ++k) {
        ulonglong2 a01 = *(const ulonglong2*)(Abase + k * 256);
        ulonglong2 a23 = *(const ulonglong2*)(Abase + k * 256 + 4);
        ulonglong2 a45 = *(const ulonglong2*)(Abase + k * 256 + 8);
        ulonglong2 a67 = *(const ulonglong2*)(Abase + k * 256 + 12);
        unsigned long long ap[8] = {a01.x, a01.y, a23.x, a23.y,
                                    a45.x, a45.y, a67.x, a67.y};
        unsigned long long wd[TN];
        #pragma unroll
        for (int j4 = 0; j4 < TN / 4; ++j4) {
            float4 w = *(const float4*)(Wbase + k * NT + j4 * 4);
            wd[j4 * 4 + 0] = fdup(w.x);
            wd[j4 * 4 + 1] = fdup(w.y);
            wd[j4 * 4 + 2] = fdup(w.z);
            wd[j4 * 4 + 3] = fdup(w.w);
        }
        #pragma unroll
        for (int i = 0; i < 8; ++i)
            #pragma unroll
            for (int j = 0; j < TN; ++j)
                ffma2(acc[i][j], ap[i], wd[j]);
    }

    // ---- epilogue ----
    float bs[TN];
    #pragma unroll
    for (int j4 = 0; j4 < TN / 4; ++j4) {
        float4 b4 = *(const float4*)&bias[bn + tx * TN + j4 * 4];
        bs[j4 * 4 + 0] = b4.x; bs[j4 * 4 + 1] = b4.y;
        bs[j4 * 4 + 2] = b4.z; bs[j4 * 4 + 3] = b4.w;
    }
    float lw[TN], lb[TN];
    if (MODE != 0) {
        #pragma unroll
        for (int j4 = 0; j4 < TN / 4; ++j4) {
            float4 w4 = *(const float4*)&lnw[tx * TN + j4 * 4];
            float4 b4 = *(const float4*)&lnb[tx * TN + j4 * 4];
            lw[j4 * 4 + 0] = w4.x; lw[j4 * 4 + 1] = w4.y;
            lw[j4 * 4 + 2] = w4.z; lw[j4 * 4 + 3] = w4.w;
            lb[j4 * 4 + 0] = b4.x; lb[j4 * 4 + 1] = b4.y;
            lb[j4 * 4 + 2] = b4.z; lb[j4 * 4 + 3] = b4.w;
        }
    }

    #pragma unroll
    for (int i2 = 0; i2 < 8; ++i2) {
        #pragma unroll
        for (int rr = 0; rr < 2; ++rr) {
            int row = bm + ty * 16 + i2 * 2 + rr;
            float v[TN];
            #pragma unroll
            for (int j = 0; j < TN; ++j) {
                float2 p = u2f(acc[i2][j]);
                v[j] = (rr ? p.y : p.x) + bs[j];
            }
            if (MODE == 0) {
                if (row < M) {
                    if (RELU) {
                        #pragma unroll
                        for (int j = 0; j < TN; ++j) v[j] = fmaxf(v[j], 0.f);
                    }
                    float* cp = C + (size_t)row * ldc + bn + tx * TN;
                    #pragma unroll
                    for (int j4 = 0; j4 < TN / 4; ++j4) {
                        float4 o;
                        o.x = v[j4 * 4 + 0]; o.y = v[j4 * 4 + 1];
                        o.z = v[j4 * 4 + 2]; o.w = v[j4 * 4 + 3];
                        *(float4*)(cp + j4 * 4) = o;
                    }
                }
            } else {
                int rc = (row < M) ? row : 0;
                int e = rc >> 2, t = rc & 3;
                int dst = edge[E + e];
                const float* res = (MODE == 1)
                    ? xres + ((size_t)dst * 4 + t) * 128 + tx * 8
                    : xres + (size_t)rc * 128 + tx * 8;
                float4 r0 = *(const float4*)(res);
                float4 r1 = *(const float4*)(res + 4);
                v[0] += r0.x; v[1] += r0.y; v[2] += r0.z; v[3] += r0.w;
                v[4] += r1.x; v[5] += r1.y; v[6] += r1.z; v[7] += r1.w;
                float s1 = 0.f, s2 = 0.f;
                #pragma unroll
                for (int j = 0; j < 8; ++j) { s1 += v[j]; s2 += v[j] * v[j]; }
                #pragma unroll
                for (int o = 1; o < 16; o <<= 1) {
                    s1 += __shfl_xor_sync(0xffffffffu, s1, o);
                    s2 += __shfl_xor_sync(0xffffffffu, s2, o);
                }
                float mu = s1 * (1.f / 128.f);
                float rs = rsqrtf(s2 * (1.f / 128.f) - mu * mu + 1e-5f);
                #pragma unroll
                for (int j = 0; j < 8; ++j) v[j] = (v[j] - mu) * rs * lw[j] + lb[j];
                if (row < M) {
                    if (MODE == 1) {
                        float* cp = C + (size_t)row * 128 + tx * 8;
                        float4 o0, o1;
                        o0.x = v[0]; o0.y = v[1]; o0.z = v[2]; o0.w = v[3];
                        o1.x = v[4]; o1.y = v[5]; o1.z = v[6]; o1.w = v[7];
                        *(float4*)cp = o0; *(float4*)(cp + 4) = o1;
                    } else {
                        float* ob = outp + ((size_t)dst * 4 + t) * 128 + tx * 8;
                        #pragma unroll
                        for (int j = 0; j < 8; ++j) atomicAdd(&ob[j], v[j]);
                    }
                }
            }
        }
    }
}

// ------------------------------- attention ----------------------------------
#define A_QD 0
#define A_KV 1536
#define A_SC 2560
#define A_SZ 2816
__global__ __launch_bounds__(256)
void attn_kernel(const int* __restrict__ edge, int E,
                 const float* __restrict__ qkvd, const float* __restrict__ kvs,
                 float* __restrict__ obuf) {
    __shared__ float sm[2 * A_SZ];
    const int tid = threadIdx.x;
    const int h = tid >> 7, lt = tid & 127;
    float* S = sm + h * A_SZ;

    int npair = (E + 1) >> 1;
    for (int p = blockIdx.x; p < npair; p += gridDim.x) {
        __syncthreads();
        int e = p * 2 + h;
        bool act = (e < E);
        if (act) {
            int src = edge[e], dst = edge[E + e];
            const float4* pq = (const float4*)(qkvd + (size_t)dst * 1536);
            const float4* pk = (const float4*)(kvs + (size_t)src * 1024);
            *(float4*)&S[A_QD + lt * 4]        = pq[lt];
            *(float4*)&S[A_QD + 512 + lt * 4]  = pq[128 + lt];
            *(float4*)&S[A_QD + 1024 + lt * 4] = pq[256 + lt];
            *(float4*)&S[A_KV + lt * 4]        = pk[lt];
            *(float4*)&S[A_KV + 512 + lt * 4]  = pk[128 + lt];
        }
        __syncthreads();
        if (act) {
            #pragma unroll
            for (int j = 0; j < 2; ++j) {
                int idx = lt * 2 + j;
                int t = idx >> 6, rem = idx & 63, s = rem >> 3, hd = rem & 7;
                const float* qp = &S[A_QD + t * 384 + hd * 16];
                const float* kp = (s < 4) ? &S[A_QD + s * 384 + 128 + hd * 16]
                                          : &S[A_KV + (s - 4) * 256 + hd * 16];
                float acc = 0.f;
                #pragma unroll
                for (int q = 0; q < 16; ++q) acc += qp[q] * kp[q];
                S[A_SC + idx] = acc * 0.25f;
            }
        }
        __syncthreads();
        if (act && lt < 32) {
            int t = lt >> 3, hd = lt & 7;
            float v[8]; float mx = -1e30f;
            #pragma unroll
            for (int s = 0; s < 8; ++s) { v[s] = S[A_SC + t * 64 + s * 8 + hd]; mx = fmaxf(mx, v[s]); }
            float sum = 0.f;
            #pragma unroll
            for (int s = 0; s < 8; ++s) { v[s] = expf(v[s] - mx); sum += v[s]; }
            float inv = 1.f / sum;
            #pragma unroll
            for (int s = 0; s < 8; ++s) S[A_SC + t * 64 + s * 8 + hd] = v[s] * inv;
        }
        __syncthreads();
        if (act) {
            int d = lt, hd = d >> 4;
            #pragma unroll
            for (int t = 0; t < 4; ++t) {
                float acc = 0.f;
                #pragma unroll
                for (int s = 0; s < 8; ++s) {
                    float pp = S[A_SC + t * 64 + s * 8 + hd];
                    float vv = (s < 4) ? S[A_QD + s * 384 + 256 + d]
                                       : S[A_KV + (s - 4) * 256 + 128 + d];
                    acc += pp * vv;
                }
                obuf[((size_t)e * 4 + t) * 128 + d] = acc;
            }
        }
    }
}

// ------------------------------- finalize -----------------------------------
__global__ void fin_kernel(float* out, const int* cnt, int NA, int NB) {
    int stride = gridDim.x * blockDim.x;
    int nA = NA * 512;
    int total = (NA + NB) * 512;
    for (int i = blockIdx.x * blockDim.x + threadIdx.x; i < total; i += stride) {
        int c;
        if (i < nA) c = cnt[NB + (i >> 9)];
        else        c = cnt[(i - nA) >> 9];
        if (c < 1) c = 1;
        out[i] = out[i] / (float)c;
    }
}

// ------------------------------- launch --------------------------------------
extern "C" void kernel_launch(void* const* d_in, const int* in_sizes, int n_in,
                              void* d_out, int out_size)
{
    const float* x_A = (const float*)d_in[0];
    const float* x_B = (const float*)d_in[1];
    const int*   eAB = (const int*)d_in[2];
    const int*   eBA = (const int*)d_in[3];
    const float* bw  = (const float*)d_in[4];
    const float* bb  = (const float*)d_in[5];
    const float* wi  = (const float*)d_in[6];
    const float* bi  = (const float*)d_in[7];
    const float* wo  = (const float*)d_in[8];
    const float* bo  = (const float*)d_in[9];
    const float* l1w = (const float*)d_in[10];
    const float* l1b = (const float*)d_in[11];
    const float* l2w = (const float*)d_in[12];
    const float* l2b = (const float*)d_in[13];
    const float* n1w = (const float*)d_in[14];
    const float* n1b = (const float*)d_in[15];
    const float* n2w = (const float*)d_in[16];
    const float* n2b = (const float*)d_in[17];
    float* out = (float*)d_out;

    int NA = in_sizes[0] / 512;
    int NB = in_sizes[1] / 512;
    int E0 = in_sizes[2] / 2;
    int E1 = in_sizes[3] / 2;

    float *qd0, *qd1, *kv0, *kv1, *weff, *beff, *b1, *b2, *b3;
    int* cnt;
    cudaGetSymbolAddress((void**)&qd0, g_qkv_dst0);
    cudaGetSymbolAddress((void**)&qd1, g_qkv_dst1);
    cudaGetSymbolAddress((void**)&kv0, g_kv_src0);
    cudaGetSymbolAddress((void**)&kv1, g_kv_src1);
    cudaGetSymbolAddress((void**)&weff, g_weff);
    cudaGetSymbolAddress((void**)&beff, g_beff);
    cudaGetSymbolAddress((void**)&cnt, g_cnt);
    cudaGetSymbolAddress((void**)&b1, g_buf1);
    cudaGetSymbolAddress((void**)&b2, g_buf2);
    cudaGetSymbolAddress((void**)&b3, g_buf3);

    const int SM128_8 = (128 * 256 + 128 * 128) * 4;  // 196608
    const int SM128_4 = (128 * 256 + 128 * 64) * 4;   // 163840
    const int SM64_8  = (64 * 256 + 64 * 128) * 4;    // 98304
    cudaFuncSetAttribute(gemm2<8, 0, false>, cudaFuncAttributeMaxDynamicSharedMemorySize, SM128_8);
    cudaFuncSetAttribute(gemm2<8, 1, false>, cudaFuncAttributeMaxDynamicSharedMemorySize, SM128_8);
    cudaFuncSetAttribute(gemm2<4, 0, true>,  cudaFuncAttributeMaxDynamicSharedMemorySize, SM128_4);
    cudaFuncSetAttribute(gemm2<8, 2, false>, cudaFuncAttributeMaxDynamicSharedMemorySize, SM64_8);

    zero_kernel<<<512, 256>>>((float4*)out, (NA + NB) * 128, cnt, NA + NB);
    prep_weff<<<dim3(256, 2), 128>>>(wi, bi, bw, bb, weff, beff);
    count_kernel<<<256, 256>>>(eAB, eBA, E0, E1, cnt, NB);

    // node precompute GEMMs
    {
        int MB = NB * 4, MA = NA * 4;
        gemm2<8, 0, false><<<dim3((MB + 255) / 256, 3), 256, SM128_8>>>(
            x_B, wi, bi, qd0, MB, 128, 384, nullptr, 0, nullptr, nullptr, nullptr, nullptr);
        gemm2<8, 0, false><<<dim3((MA + 255) / 256, 2), 256, SM128_8>>>(
            x_A, weff, beff, kv0, MA, 128, 256, nullptr, 0, nullptr, nullptr, nullptr, nullptr);
        gemm2<8, 0, false><<<dim3((MA + 255) / 256, 3), 256, SM128_8>>>(
            x_A, wi + 384 * 128, bi + 384, qd1, MA, 128, 384, nullptr, 0, nullptr, nullptr, nullptr, nullptr);
        gemm2<8, 0, false><<<dim3((MB + 255) / 256, 2), 256, SM128_8>>>(
            x_B, weff + 256 * 128, beff + 256, kv1, MB, 128, 256, nullptr, 0, nullptr, nullptr, nullptr, nullptr);
    }

    // ---- relation 0: A->B updates B ----
    {
        int E = E0, M = E0 * 4;
        float* outB = out + (size_t)NA * 512;
        attn_kernel<<<2048, 256>>>(eAB, E, qd0, kv0, b1);
        gemm2<8, 1, false><<<dim3((M + 255) / 256, 1), 256, SM128_8>>>(
            b1, wo, bo, b2, M, 128, 128, eAB, E, x_B, n1w, n1b, nullptr);
        gemm2<4, 0, true><<<dim3((M + 255) / 256, 1), 256, SM128_4>>>(
            b2, l1w, l1b, b3, M, 128, 64, nullptr, 0, nullptr, nullptr, nullptr, nullptr);
        gemm2<8, 2, false><<<dim3((M + 255) / 256, 1), 256, SM64_8>>>(
            b3, l2w, l2b, nullptr, M, 64, 0, eAB, E, b2, n2w, n2b, outB);
    }
    // ---- relation 1: B->A updates A ----
    {
        int E = E1, M = E1 * 4;
        attn_kernel<<<2048, 256>>>(eBA, E, qd1, kv1, b1);
        gemm2<8, 1, false><<<dim3((M + 255) / 256, 1), 256, SM128_8>>>(
            b1, wo + 16384, bo + 128, b2, M, 128, 128, eBA, E, x_A, n1w + 128, n1b + 128, nullptr);
        gemm2<4, 0, true><<<dim3((M + 255) / 256, 1), 256, SM128_4>>>(
            b2, l1w + 8192, l1b + 64, b3, M, 128, 64, nullptr, 0, nullptr, nullptr, nullptr, nullptr);
        gemm2<8, 2, false><<<dim3((M + 255) / 256, 1), 256, SM64_8>>>(
            b3, l2w + 8192, l2b + 128, nullptr, M, 64, 0, eBA, E, b2, n2w + 128, n2b + 128, out);
    }

    fin_kernel<<<512, 256>>>(out, cnt, NA, NB);
}

// round 6
// speedup vs baseline: 1.2135x; 1.2135x over previous
#include <cuda_runtime.h>
#include <mma.h>
#include <math.h>

using namespace nvcuda;

// ============================================================================
// DBTransformerLayer — R2 dataflow + tf32 wmma GEMMs + fused LN epilogues.
//  Node: qkv_dst = x_dst @ Wi^T + bi ; kv_src = x_src @ Weff^T + beff
//  Edge: attn -> o ; [wo GEMM + residual(gather) + LN1] -> xln ;
//        [l1 GEMM relu] -> h ; [l2 GEMM + residual + LN2 + atomic scatter]
//  counts ; divide.
// ============================================================================

#define MAX_N 20000
#define MAX_E 100000

__device__ float g_qkv_dst0[(size_t)MAX_N * 4 * 384];
__device__ float g_qkv_dst1[(size_t)MAX_N * 4 * 384];
__device__ float g_kv_src0[(size_t)MAX_N * 4 * 256];
__device__ float g_kv_src1[(size_t)MAX_N * 4 * 256];
__device__ float g_weff[2 * 256 * 128];
__device__ float g_beff[2 * 256];
__device__ int   g_cnt[2 * MAX_N];
__device__ float g_buf1[(size_t)MAX_E * 512];   // o (attn out)
__device__ float g_buf2[(size_t)MAX_E * 512];   // xln
__device__ float g_buf3[(size_t)MAX_E * 256];   // h

// ------------------------------- zero --------------------------------------
__global__ void zero_kernel(float4* out, int n4, int* cnt, int nc) {
    int stride = gridDim.x * blockDim.x;
    for (int i = blockIdx.x * blockDim.x + threadIdx.x; i < n4; i += stride)
        out[i] = make_float4(0.f, 0.f, 0.f, 0.f);
    for (int i = blockIdx.x * blockDim.x + threadIdx.x; i < nc; i += stride) cnt[i] = 0;
}

// ------------------------------- counts ------------------------------------
__global__ void count_kernel(const int* __restrict__ eAB, const int* __restrict__ eBA,
                             int E0, int E1, int* cnt, int NB) {
    int stride = gridDim.x * blockDim.x;
    int total = E0 + E1;
    for (int i = blockIdx.x * blockDim.x + threadIdx.x; i < total; i += stride) {
        if (i < E0) atomicAdd(&cnt[eAB[E0 + i]], 1);
        else        atomicAdd(&cnt[NB + eBA[E1 + (i - E0)]], 1);
    }
}

// ------------------------ Weff = Wi[128:384] @ bw ---------------------------
__global__ void prep_weff(const float* __restrict__ wi, const float* __restrict__ bi,
                          const float* __restrict__ bw, const float* __restrict__ bb,
                          float* __restrict__ weff, float* __restrict__ beff) {
    int n = blockIdx.x, r = blockIdx.y, k = threadIdx.x;
    const float* wrow = wi + ((size_t)r * 384 + 128 + n) * 128;
    const float* bwr  = bw + (size_t)r * 16384;
    float acc = 0.f;
    for (int m = 0; m < 128; ++m) acc += wrow[m] * bwr[m * 128 + k];
    weff[((size_t)r * 256 + n) * 128 + k] = acc;

    __shared__ float red[128];
    red[k] = wrow[k] * bb[r * 128 + k];
    __syncthreads();
    for (int s = 64; s; s >>= 1) { if (k < s) red[k] += red[k + s]; __syncthreads(); }
    if (k == 0) beff[r * 256 + n] = bi[(size_t)r * 384 + 128 + n] + red[0];
}

// ---------- tf32 wmma GEMM, tile 128(M) x 64(N): plain store (+relu) --------
// C[M,Nout] = A[M,K] @ W[Nout,K]^T + b ; col block = blockIdx.y*64
__global__ __launch_bounds__(256)
void gemm_n64(const float* __restrict__ A, const float* __restrict__ W,
              const float* __restrict__ bias, float* __restrict__ C,
              int M, int Nout, int K, int relu) {
    __shared__ float sm[8704];               // max(128*36+64*36, 128*68)
    float* As = sm;                          // [128][36]
    float* Ws = sm + 128 * 36;               // [64][36]
    float* Cs = sm;                          // [128][68]
    const int bm = blockIdx.x * 128, bn = blockIdx.y * 64;
    const int tid = threadIdx.x;
    const int warpId = tid >> 5;
    const int wm = warpId & 3, wn = warpId >> 2;

    wmma::fragment<wmma::accumulator, 16, 16, 8, float> c00, c01, c10, c11;
    wmma::fill_fragment(c00, 0.f); wmma::fill_fragment(c01, 0.f);
    wmma::fill_fragment(c10, 0.f); wmma::fill_fragment(c11, 0.f);

    for (int kc = 0; kc < K; kc += 32) {
        __syncthreads();
        #pragma unroll
        for (int it = 0; it < 4; ++it) {
            int idx = tid + it * 256;
            int row = idx >> 3, kq = idx & 7;
            int gm = bm + row;
            float4 a = make_float4(0.f, 0.f, 0.f, 0.f);
            if (gm < M) a = *(const float4*)&A[(size_t)gm * K + kc + kq * 4];
            *(float4*)&As[row * 36 + kq * 4] = a;
        }
        #pragma unroll
        for (int it = 0; it < 2; ++it) {
            int idx = tid + it * 256;
            int n = idx >> 3, kq = idx & 7;
            float4 w = *(const float4*)&W[(size_t)(bn + n) * K + kc + kq * 4];
            *(float4*)&Ws[n * 36 + kq * 4] = w;
        }
        __syncthreads();

        #pragma unroll
        for (int ks = 0; ks < 4; ++ks) {
            wmma::fragment<wmma::matrix_a, 16, 16, 8, wmma::precision::tf32, wmma::row_major> a0, a1;
            wmma::fragment<wmma::matrix_b, 16, 16, 8, wmma::precision::tf32, wmma::col_major> b0, b1;
            wmma::load_matrix_sync(a0, &As[(wm * 32) * 36 + ks * 8], 36);
            wmma::load_matrix_sync(a1, &As[(wm * 32 + 16) * 36 + ks * 8], 36);
            wmma::load_matrix_sync(b0, &Ws[(wn * 32) * 36 + ks * 8], 36);
            wmma::load_matrix_sync(b1, &Ws[(wn * 32 + 16) * 36 + ks * 8], 36);
            #pragma unroll
            for (int t = 0; t < a0.num_elements; ++t) {
                a0.x[t] = wmma::__float_to_tf32(a0.x[t]);
                a1.x[t] = wmma::__float_to_tf32(a1.x[t]);
            }
            #pragma unroll
            for (int t = 0; t < b0.num_elements; ++t) {
                b0.x[t] = wmma::__float_to_tf32(b0.x[t]);
                b1.x[t] = wmma::__float_to_tf32(b1.x[t]);
            }
            wmma::mma_sync(c00, a0, b0, c00);
            wmma::mma_sync(c01, a0, b1, c01);
            wmma::mma_sync(c10, a1, b0, c10);
            wmma::mma_sync(c11, a1, b1, c11);
        }
    }
    __syncthreads();
    wmma::store_matrix_sync(&Cs[(wm * 32) * 68 + wn * 32], c00, 68, wmma::mem_row_major);
    wmma::store_matrix_sync(&Cs[(wm * 32) * 68 + wn * 32 + 16], c01, 68, wmma::mem_row_major);
    wmma::store_matrix_sync(&Cs[(wm * 32 + 16) * 68 + wn * 32], c10, 68, wmma::mem_row_major);
    wmma::store_matrix_sync(&Cs[(wm * 32 + 16) * 68 + wn * 32 + 16], c11, 68, wmma::mem_row_major);
    __syncthreads();

    int row = tid >> 1, ch = (tid & 1) * 32;
    int gm = bm + row;
    if (gm < M) {
        float* cp = C + (size_t)gm * Nout + bn + ch;
        #pragma unroll
        for (int j4 = 0; j4 < 8; ++j4) {
            float4 v = *(const float4*)&Cs[row * 68 + ch + j4 * 4];
            float4 b4 = *(const float4*)&bias[bn + ch + j4 * 4];
            v.x += b4.x; v.y += b4.y; v.z += b4.z; v.w += b4.w;
            if (relu) {
                v.x = fmaxf(v.x, 0.f); v.y = fmaxf(v.y, 0.f);
                v.z = fmaxf(v.z, 0.f); v.w = fmaxf(v.w, 0.f);
            }
            *(float4*)(cp + j4 * 4) = v;
        }
    }
}

// ---- tf32 wmma GEMM, tile 64(M) x 128(N) + residual + LN (+scatter) --------
// MODE 1: residual = xres[(edge_dst(e)*4+t)*128+..] ; store LN -> C[row*128..]
// MODE 2: residual = xres[row*128+..] ; atomicAdd LN -> outp[(dst*4+t)*128..]
template<int MODE>
__global__ __launch_bounds__(256)
void gemm_ln(const float* __restrict__ A, const float* __restrict__ W,
             const float* __restrict__ bias, float* __restrict__ C,
             int M, int K,
             const int* __restrict__ edge, int E,
             const float* __restrict__ xres,
             const float* __restrict__ lnw, const float* __restrict__ lnb,
             float* __restrict__ outp)
{
    __shared__ float sm[8448];               // max(64*36+128*36, 64*132)
    float* As = sm;                          // [64][36]
    float* Ws = sm + 64 * 36;                // [128][36]
    float* Cs = sm;                          // [64][132]
    const int bm = blockIdx.x * 64;
    const int tid = threadIdx.x;
    const int warpId = tid >> 5, lane = tid & 31;
    const int wm = warpId & 1, wn = warpId >> 1;

    wmma::fragment<wmma::accumulator, 16, 16, 8, float> c00, c01, c10, c11;
    wmma::fill_fragment(c00, 0.f); wmma::fill_fragment(c01, 0.f);
    wmma::fill_fragment(c10, 0.f); wmma::fill_fragment(c11, 0.f);

    for (int kc = 0; kc < K; kc += 32) {
        __syncthreads();
        #pragma unroll
        for (int it = 0; it < 2; ++it) {
            int idx = tid + it * 256;
            int row = idx >> 3, kq = idx & 7;
            int gm = bm + row;
            float4 a = make_float4(0.f, 0.f, 0.f, 0.f);
            if (gm < M) a = *(const float4*)&A[(size_t)gm * K + kc + kq * 4];
            *(float4*)&As[row * 36 + kq * 4] = a;
        }
        #pragma unroll
        for (int it = 0; it < 4; ++it) {
            int idx = tid + it * 256;
            int n = idx >> 3, kq = idx & 7;
            float4 w = *(const float4*)&W[(size_t)n * K + kc + kq * 4];
            *(float4*)&Ws[n * 36 + kq * 4] = w;
        }
        __syncthreads();

        #pragma unroll
        for (int ks = 0; ks < 4; ++ks) {
            wmma::fragment<wmma::matrix_a, 16, 16, 8, wmma::precision::tf32, wmma::row_major> a0, a1;
            wmma::fragment<wmma::matrix_b, 16, 16, 8, wmma::precision::tf32, wmma::col_major> b0, b1;
            wmma::load_matrix_sync(a0, &As[(wm * 32) * 36 + ks * 8], 36);
            wmma::load_matrix_sync(a1, &As[(wm * 32 + 16) * 36 + ks * 8], 36);
            wmma::load_matrix_sync(b0, &Ws[(wn * 32) * 36 + ks * 8], 36);
            wmma::load_matrix_sync(b1, &Ws[(wn * 32 + 16) * 36 + ks * 8], 36);
            #pragma unroll
            for (int t = 0; t < a0.num_elements; ++t) {
                a0.x[t] = wmma::__float_to_tf32(a0.x[t]);
                a1.x[t] = wmma::__float_to_tf32(a1.x[t]);
            }
            #pragma unroll
            for (int t = 0; t < b0.num_elements; ++t) {
                b0.x[t] = wmma::__float_to_tf32(b0.x[t]);
                b1.x[t] = wmma::__float_to_tf32(b1.x[t]);
            }
            wmma::mma_sync(c00, a0, b0, c00);
            wmma::mma_sync(c01, a0, b1, c01);
            wmma::mma_sync(c10, a1, b0, c10);
            wmma::mma_sync(c11, a1, b1, c11);
        }
    }
    __syncthreads();
    wmma::store_matrix_sync(&Cs[(wm * 32) * 132 + wn * 32], c00, 132, wmma::mem_row_major);
    wmma::store_matrix_sync(&Cs[(wm * 32) * 132 + wn * 32 + 16], c01, 132, wmma::mem_row_major);
    wmma::store_matrix_sync(&Cs[(wm * 32 + 16) * 132 + wn * 32], c10, 132, wmma::mem_row_major);
    wmma::store_matrix_sync(&Cs[(wm * 32 + 16) * 132 + wn * 32 + 16], c11, 132, wmma::mem_row_major);
    __syncthreads();

    float4 b4 = *(const float4*)&bias[lane * 4];
    float4 w4 = *(const float4*)&lnw[lane * 4];
    float4 g4 = *(const float4*)&lnb[lane * 4];

    #pragma unroll
    for (int rr = 0; rr < 8; ++rr) {
        int lr = warpId * 8 + rr;
        int r = bm + lr;
        int rc = (r < M) ? r : 0;
        int e = rc >> 2, t = rc & 3;
        int dst = edge[E + e];
        const float* resp = (MODE == 1)
            ? xres + ((size_t)dst * 4 + t) * 128 + lane * 4
            : xres + (size_t)rc * 128 + lane * 4;
        float4 x = *(const float4*)resp;
        float4 c = *(const float4*)&Cs[lr * 132 + lane * 4];
        float v0 = c.x + b4.x + x.x;
        float v1 = c.y + b4.y + x.y;
        float v2 = c.z + b4.z + x.z;
        float v3 = c.w + b4.w + x.w;
        float s1 = v0 + v1 + v2 + v3;
        float s2 = v0 * v0 + v1 * v1 + v2 * v2 + v3 * v3;
        #pragma unroll
        for (int o = 16; o; o >>= 1) {
            s1 += __shfl_xor_sync(0xffffffffu, s1, o);
            s2 += __shfl_xor_sync(0xffffffffu, s2, o);
        }
        float mu = s1 * (1.f / 128.f);
        float rs = rsqrtf(s2 * (1.f / 128.f) - mu * mu + 1e-5f);
        float o0 = (v0 - mu) * rs * w4.x + g4.x;
        float o1 = (v1 - mu) * rs * w4.y + g4.y;
        float o2 = (v2 - mu) * rs * w4.z + g4.z;
        float o3 = (v3 - mu) * rs * w4.w + g4.w;
        if (r < M) {
            if (MODE == 1) {
                float4 o4v; o4v.x = o0; o4v.y = o1; o4v.z = o2; o4v.w = o3;
                *(float4*)&C[(size_t)r * 128 + lane * 4] = o4v;
            } else {
                float* ob = outp + ((size_t)dst * 4 + t) * 128 + lane * 4;
                atomicAdd(&ob[0], o0); atomicAdd(&ob[1], o1);
                atomicAdd(&ob[2], o2); atomicAdd(&ob[3], o3);
            }
        }
    }
}

// ------------------------------- attention ----------------------------------
#define A_QD 0
#define A_KV 1536
#define A_SC 2560
#define A_SZ 2816
__global__ __launch_bounds__(256)
void attn_kernel(const int* __restrict__ edge, int E,
                 const float* __restrict__ qkvd, const float* __restrict__ kvs,
                 float* __restrict__ obuf) {
    __shared__ float sm[2 * A_SZ];
    const int tid = threadIdx.x;
    const int h = tid >> 7, lt = tid & 127;
    float* S = sm + h * A_SZ;

    int npair = (E + 1) >> 1;
    for (int p = blockIdx.x; p < npair; p += gridDim.x) {
        __syncthreads();
        int e = p * 2 + h;
        bool act = (e < E);
        if (act) {
            int src = edge[e], dst = edge[E + e];
            const float4* pq = (const float4*)(qkvd + (size_t)dst * 1536);
            const float4* pk = (const float4*)(kvs + (size_t)src * 1024);
            *(float4*)&S[A_QD + lt * 4]        = pq[lt];
            *(float4*)&S[A_QD + 512 + lt * 4]  = pq[128 + lt];
            *(float4*)&S[A_QD + 1024 + lt * 4] = pq[256 + lt];
            *(float4*)&S[A_KV + lt * 4]        = pk[lt];
            *(float4*)&S[A_KV + 512 + lt * 4]  = pk[128 + lt];
        }
        __syncthreads();
        if (act) {
            #pragma unroll
            for (int j = 0; j < 2; ++j) {
                int idx = lt * 2 + j;
                int t = idx >> 6, rem = idx & 63, s = rem >> 3, hd = rem & 7;
                const float* qp = &S[A_QD + t * 384 + hd * 16];
                const float* kp = (s < 4) ? &S[A_QD + s * 384 + 128 + hd * 16]
                                          : &S[A_KV + (s - 4) * 256 + hd * 16];
                float acc = 0.f;
                #pragma unroll
                for (int q = 0; q < 16; ++q) acc += qp[q] * kp[q];
                S[A_SC + idx] = acc * 0.25f;
            }
        }
        __syncthreads();
        if (act && lt < 32) {
            int t = lt >> 3, hd = lt & 7;
            float v[8]; float mx = -1e30f;
            #pragma unroll
            for (int s = 0; s < 8; ++s) { v[s] = S[A_SC + t * 64 + s * 8 + hd]; mx = fmaxf(mx, v[s]); }
            float sum = 0.f;
            #pragma unroll
            for (int s = 0; s < 8; ++s) { v[s] = expf(v[s] - mx); sum += v[s]; }
            float inv = 1.f / sum;
            #pragma unroll
            for (int s = 0; s < 8; ++s) S[A_SC + t * 64 + s * 8 + hd] = v[s] * inv;
        }
        __syncthreads();
        if (act) {
            int d = lt, hd = d >> 4;
            #pragma unroll
            for (int t = 0; t < 4; ++t) {
                float acc = 0.f;
                #pragma unroll
                for (int s = 0; s < 8; ++s) {
                    float pp = S[A_SC + t * 64 + s * 8 + hd];
                    float vv = (s < 4) ? S[A_QD + s * 384 + 256 + d]
                                       : S[A_KV + (s - 4) * 256 + 128 + d];
                    acc += pp * vv;
                }
                obuf[((size_t)e * 4 + t) * 128 + d] = acc;
            }
        }
    }
}

// ------------------------------- finalize -----------------------------------
__global__ void fin_kernel(float* out, const int* cnt, int NA, int NB) {
    int stride = gridDim.x * blockDim.x;
    int nA = NA * 512;
    int total = (NA + NB) * 512;
    for (int i = blockIdx.x * blockDim.x + threadIdx.x; i < total; i += stride) {
        int c;
        if (i < nA) c = cnt[NB + (i >> 9)];
        else        c = cnt[(i - nA) >> 9];
        if (c < 1) c = 1;
        out[i] = out[i] / (float)c;
    }
}

// ------------------------------- launch --------------------------------------
extern "C" void kernel_launch(void* const* d_in, const int* in_sizes, int n_in,
                              void* d_out, int out_size)
{
    const float* x_A = (const float*)d_in[0];
    const float* x_B = (const float*)d_in[1];
    const int*   eAB = (const int*)d_in[2];
    const int*   eBA = (const int*)d_in[3];
    const float* bw  = (const float*)d_in[4];
    const float* bb  = (const float*)d_in[5];
    const float* wi  = (const float*)d_in[6];
    const float* bi  = (const float*)d_in[7];
    const float* wo  = (const float*)d_in[8];
    const float* bo  = (const float*)d_in[9];
    const float* l1w = (const float*)d_in[10];
    const float* l1b = (const float*)d_in[11];
    const float* l2w = (const float*)d_in[12];
    const float* l2b = (const float*)d_in[13];
    const float* n1w = (const float*)d_in[14];
    const float* n1b = (const float*)d_in[15];
    const float* n2w = (const float*)d_in[16];
    const float* n2b = (const float*)d_in[17];
    float* out = (float*)d_out;

    int NA = in_sizes[0] / 512;
    int NB = in_sizes[1] / 512;
    int E0 = in_sizes[2] / 2;
    int E1 = in_sizes[3] / 2;

    float *qd0, *qd1, *kv0, *kv1, *weff, *beff, *b1, *b2, *b3;
    int* cnt;
    cudaGetSymbolAddress((void**)&qd0, g_qkv_dst0);
    cudaGetSymbolAddress((void**)&qd1, g_qkv_dst1);
    cudaGetSymbolAddress((void**)&kv0, g_kv_src0);
    cudaGetSymbolAddress((void**)&kv1, g_kv_src1);
    cudaGetSymbolAddress((void**)&weff, g_weff);
    cudaGetSymbolAddress((void**)&beff, g_beff);
    cudaGetSymbolAddress((void**)&cnt, g_cnt);
    cudaGetSymbolAddress((void**)&b1, g_buf1);
    cudaGetSymbolAddress((void**)&b2, g_buf2);
    cudaGetSymbolAddress((void**)&b3, g_buf3);

    zero_kernel<<<512, 256>>>((float4*)out, (NA + NB) * 128, cnt, NA + NB);
    prep_weff<<<dim3(256, 2), 128>>>(wi, bi, bw, bb, weff, beff);
    count_kernel<<<256, 256>>>(eAB, eBA, E0, E1, cnt, NB);

    // node precompute GEMMs
    {
        int MB = NB * 4, MA = NA * 4;
        gemm_n64<<<dim3((MB + 127) / 128, 6), 256>>>(x_B, wi,               bi,         qd0, MB, 384, 128, 0);
        gemm_n64<<<dim3((MA + 127) / 128, 4), 256>>>(x_A, weff,             beff,       kv0, MA, 256, 128, 0);
        gemm_n64<<<dim3((MA + 127) / 128, 6), 256>>>(x_A, wi + 384 * 128,   bi + 384,   qd1, MA, 384, 128, 0);
        gemm_n64<<<dim3((MB + 127) / 128, 4), 256>>>(x_B, weff + 256 * 128, beff + 256, kv1, MB, 256, 128, 0);
    }

    // ---- relation 0: A->B updates B ----
    {
        int E = E0, M = E0 * 4;
        float* outB = out + (size_t)NA * 512;
        attn_kernel<<<2048, 256>>>(eAB, E, qd0, kv0, b1);
        gemm_ln<1><<<(M + 63) / 64, 256>>>(b1, wo, bo, b2, M, 128, eAB, E, x_B, n1w, n1b, nullptr);
        gemm_n64<<<dim3((M + 127) / 128, 1), 256>>>(b2, l1w, l1b, b3, M, 64, 128, 1);
        gemm_ln<2><<<(M + 63) / 64, 256>>>(b3, l2w, l2b, nullptr, M, 64, eAB, E, b2, n2w, n2b, outB);
    }
    // ---- relation 1: B->A updates A ----
    {
        int E = E1, M = E1 * 4;
        attn_kernel<<<2048, 256>>>(eBA, E, qd1, kv1, b1);
        gemm_ln<1><<<(M + 63) / 64, 256>>>(b1, wo + 16384, bo + 128, b2, M, 128, eBA, E, x_A, n1w + 128, n1b + 128, nullptr);
        gemm_n64<<<dim3((M + 127) / 128, 1), 256>>>(b2, l1w + 8192, l1b + 64, b3, M, 64, 128, 1);
        gemm_ln<2><<<(M + 63) / 64, 256>>>(b3, l2w + 8192, l2b + 128, nullptr, M, 64, eBA, E, b2, n2w + 128, n2b + 128, out);
    }

    fin_kernel<<<512, 256>>>(out, cnt, NA, NB);
}